// round 17
// baseline (speedup 1.0000x reference)
#include <cuda_runtime.h>
#include <cuda_bf16.h>

#define SIDE 9
#define STATE 81
#define NA 5
#define H 32
#define WARPS_K1 8
#define MAX_B 131072
#define K2T 256                 // K2 threads; block covers 2*K2T rows

// nsc transposed scratch: [d][b]
__device__ float g_nscT[(size_t)STATE * MAX_B];

// Weights in constant memory: warp-uniform reads go through the constant
// port (LDC/LDCU), off the L1tex pipe.
__constant__ float cW1[STATE * H];
__constant__ float cW2[H * H];
__constant__ float cW3[H];
__constant__ float cb3[1];

// ---------------------------------------------------------------------------
// K1: warp-per-row scatter + reward + transposed scratch write (R16 form).
// ---------------------------------------------------------------------------
__global__ __launch_bounds__(32 * WARPS_K1) void k1_nsc_reward(
    const float* __restrict__ obs,
    const float* __restrict__ acr_g,
    float* __restrict__ out,
    int B)
{
    __shared__ float s_ac[WARPS_K1][416];
    __shared__ float s_nsc[WARPS_K1 * STATE];

    const int tid  = threadIdx.x;
    const int wid  = tid >> 5;
    const int lane = tid & 31;
    const long long row0 = (long long)blockIdx.x * WARPS_K1;
    const long long row  = row0 + wid;

    if (row < B) {
        const float* __restrict__ acr = acr_g + row * (STATE * NA);
        float* __restrict__ sp = s_ac[wid];
        #pragma unroll
        for (int k = 0; k < 13; k++) {
            const int i = lane + 32 * k;
            if (i < STATE * NA) sp[i] = __ldg(&acr[i]);
        }
        __syncwarp();

        const float* __restrict__ dem = obs + row * (3 * STATE) + 2 * STATE;
        float* __restrict__ nout = out + 3LL * B + row * STATE;
        float* __restrict__ nrow = s_nsc + wid * STATE;

        float imm = 0.0f;
        #pragma unroll
        for (int k = 0; k < 3; k++) {
            const int c = lane + 32 * k;
            if (c < STATE) {
                const int r   = c / SIDE;
                const int col = c - r * SIDE;
                float v = sp[c * NA + 0];
                if (r == 0)        v += sp[c * NA + 1];
                if (r < SIDE - 1)  v += sp[(c + SIDE) * NA + 1];
                if (r == SIDE - 1) v += sp[c * NA + 2];
                if (r > 0)         v += sp[(c - SIDE) * NA + 2];
                if (col == 0)      v += sp[c * NA + 3];
                if (col < SIDE - 1)v += sp[(c + 1) * NA + 3];
                if (col == SIDE-1) v += sp[c * NA + 4];
                if (col > 0)       v += sp[(c - 1) * NA + 4];

                nout[c] = v;
                nrow[c] = v;
                imm += fminf(v, __ldg(&dem[c]));
            }
        }

        #pragma unroll
        for (int o = 16; o; o >>= 1) imm += __shfl_xor_sync(0xffffffffu, imm, o);
        if (lane == 0) out[(long long)B + row] = imm;
    }
    __syncthreads();

    for (int i = tid; i < STATE * WARPS_K1; i += 32 * WARPS_K1) {
        const int d = i >> 3;
        const int j = i & 7;
        if (row0 + j < B)
            g_nscT[(long long)d * B + row0 + j] = s_nsc[j * STATE + d];
    }
}

// ---------------------------------------------------------------------------
// Packed f32x2 helpers
// ---------------------------------------------------------------------------
__device__ __forceinline__ unsigned long long pack2(float x) {
    unsigned long long r;
    asm("mov.b64 %0, {%1, %1};" : "=l"(r) : "f"(x));
    return r;
}
__device__ __forceinline__ void ffma2(unsigned long long& d,
                                      unsigned long long a,
                                      unsigned long long b) {
    asm("fma.rn.f32x2 %0, %1, %2, %0;" : "+l"(d) : "l"(a), "l"(b));
}
__device__ __forceinline__ void unpack2(unsigned long long p, float& lo, float& hi) {
    asm("mov.b64 {%0, %1}, %2;" : "=f"(lo), "=f"(hi) : "l"(p));
}
__device__ __forceinline__ unsigned long long cpair(const float* p) {
    // 8-byte constant-memory read (uniform address -> constant port).
    return *reinterpret_cast<const unsigned long long*>(p);
}

// ---------------------------------------------------------------------------
// K2: R16 structure (2 rows/thread, two 16-column passes, h1 parked in smem
// per-thread-column) with weights in __constant__ -> weight reads leave the
// L1tex pipe. No block barriers at all.
// ---------------------------------------------------------------------------
__global__ __launch_bounds__(K2T) void k2_mlp(
    float* __restrict__ out,
    int B)
{
    extern __shared__ float s_h1[];           // 2 rows * 32 cols * K2T

    const int tid = threadIdx.x;
    const long long base = (long long)blockIdx.x * (2 * K2T);
    const long long b0 = base + tid;
    const long long b1 = base + K2T + tid;
    const bool ok0 = (b0 < B), ok1 = (b1 < B);
    const long long c0 = ok0 ? b0 : (long long)(B - 1);
    const long long c1 = ok1 ? b1 : (long long)(B - 1);

    const float imm0 = __ldg(&out[(long long)B + c0]);
    const float imm1 = __ldg(&out[(long long)B + c1]);

    // ---- Layer 1: two passes of 16 columns over both rows ----
    #pragma unroll
    for (int p = 0; p < 2; p++) {
        const int cb = 16 * p;
        unsigned long long a[16];
        #pragma unroll
        for (int j = 0; j < 16; j++) a[j] = 0ULL;

        #pragma unroll 9
        for (int d = 0; d < STATE; d++) {
            const unsigned long long va =
                pack2(__ldg(&g_nscT[(long long)d * B + c0]));
            const unsigned long long vb =
                pack2(__ldg(&g_nscT[(long long)d * B + c1]));
            const float* wrow = &cW1[d * H + cb];
            #pragma unroll
            for (int j = 0; j < 8; j++) {
                const unsigned long long w = cpair(wrow + 2 * j);
                ffma2(a[j],     va, w);
                ffma2(a[8 + j], vb, w);
            }
        }

        #pragma unroll
        for (int j = 0; j < 8; j++) {
            float lo, hi;
            unpack2(a[j], lo, hi);
            s_h1[(0 * H + cb + 2 * j + 0) * K2T + tid] = fmaxf(lo, 0.0f);
            s_h1[(0 * H + cb + 2 * j + 1) * K2T + tid] = fmaxf(hi, 0.0f);
            unpack2(a[8 + j], lo, hi);
            s_h1[(1 * H + cb + 2 * j + 0) * K2T + tid] = fmaxf(lo, 0.0f);
            s_h1[(1 * H + cb + 2 * j + 1) * K2T + tid] = fmaxf(hi, 0.0f);
        }
    }

    // ---- Layer 2 + head: two passes of 16 columns over both rows ----
    float ret0 = cb3[0], ret1 = cb3[0];
    #pragma unroll
    for (int q = 0; q < 2; q++) {
        const int cb = 16 * q;
        unsigned long long z[16];
        #pragma unroll
        for (int j = 0; j < 16; j++) z[j] = 0ULL;

        #pragma unroll
        for (int i = 0; i < H; i++) {
            const unsigned long long va = pack2(s_h1[(0 * H + i) * K2T + tid]);
            const unsigned long long vb = pack2(s_h1[(1 * H + i) * K2T + tid]);
            const float* wrow = &cW2[i * H + cb];
            #pragma unroll
            for (int j = 0; j < 8; j++) {
                const unsigned long long w = cpair(wrow + 2 * j);
                ffma2(z[j],     va, w);
                ffma2(z[8 + j], vb, w);
            }
        }

        #pragma unroll
        for (int j = 0; j < 8; j++) {
            float lo, hi;
            unpack2(z[j], lo, hi);
            ret0 += fmaxf(lo, 0.0f) * cW3[cb + 2 * j]
                  + fmaxf(hi, 0.0f) * cW3[cb + 2 * j + 1];
            unpack2(z[8 + j], lo, hi);
            ret1 += fmaxf(lo, 0.0f) * cW3[cb + 2 * j]
                  + fmaxf(hi, 0.0f) * cW3[cb + 2 * j + 1];
        }
    }

    if (ok0) {
        out[b0]                      = imm0 + ret0;
        out[2LL * (long long)B + b0] = ret0;
    }
    if (ok1) {
        out[b1]                      = imm1 + ret1;
        out[2LL * (long long)B + b1] = ret1;
    }
}

static const int K2_SMEM_BYTES = (2 * H * K2T) * (int)sizeof(float);

extern "C" void kernel_launch(void* const* d_in, const int* in_sizes, int n_in,
                              void* d_out, int out_size) {
    const float* obs = (const float*)d_in[0];
    const float* action_count = (const float*)d_in[1];
    const float* W1 = (const float*)d_in[2];
    const float* W2 = (const float*)d_in[3];
    const float* W3 = (const float*)d_in[4];
    const float* b3 = (const float*)d_in[5];
    float* out = (float*)d_out;

    const int B = in_sizes[0] / (3 * STATE);

    // Stage weights into constant memory (D2D async memcpy nodes; capturable).
    cudaMemcpyToSymbolAsync(cW1, W1, STATE * H * sizeof(float), 0,
                            cudaMemcpyDeviceToDevice, 0);
    cudaMemcpyToSymbolAsync(cW2, W2, H * H * sizeof(float), 0,
                            cudaMemcpyDeviceToDevice, 0);
    cudaMemcpyToSymbolAsync(cW3, W3, H * sizeof(float), 0,
                            cudaMemcpyDeviceToDevice, 0);
    cudaMemcpyToSymbolAsync(cb3, b3, sizeof(float), 0,
                            cudaMemcpyDeviceToDevice, 0);

    cudaFuncSetAttribute(k2_mlp, cudaFuncAttributeMaxDynamicSharedMemorySize,
                         K2_SMEM_BYTES);

    const int blocks1 = (B + WARPS_K1 - 1) / WARPS_K1;
    k1_nsc_reward<<<blocks1, 32 * WARPS_K1>>>(obs, action_count, out, B);

    const int rows2 = 2 * K2T;
    const int blocks2 = (B + rows2 - 1) / rows2;
    k2_mlp<<<blocks2, K2T, K2_SMEM_BYTES>>>(out, B);
}